// round 15
// baseline (speedup 1.0000x reference)
#include <cuda_runtime.h>

#define NUM_B 2
#define NUM_S 2048
#define NUM_D 1024
#define NUM_H 16
#define HDIM  64

// ---------------- scratch (device globals; no allocation allowed) ----------
// Q/K are stored with the head-dim interleaved within each 8-group:
// orig col c sits at position p(c) = ((c&3)<<1)|(c>>2)  (order 0,4,1,5,2,6,3,7)
// Applied to BOTH Q and K -> QK^T contraction unchanged (bit-identical).
__device__ float g_Q [NUM_B * NUM_H * NUM_S * HDIM];  // [bh][s][d-perm] x0.125*log2e, tf32-rounded
__device__ float g_K [NUM_B * NUM_H * NUM_S * HDIM];  // [bh][s][d-perm] tf32-rounded
__device__ float g_V [NUM_B * NUM_H * NUM_S * HDIM];  // [bh][s][d] full fp32 (exclusion)
__device__ float g_Vr[NUM_B * NUM_H * NUM_S * HDIM];  // [bh][s][d] tf32-rounded (PV mma)
__device__ float g_Oc[NUM_B * NUM_S * NUM_D];         // [b,s,d] post-exclusion, full fp32
__device__ float g_dummy;

// ---------------- helpers --------------------------------------------------
__device__ __forceinline__ unsigned rnd(float x) { return __float_as_uint(x) + 0x1000u; }
__device__ __forceinline__ float rndf(float x) { return __uint_as_float(rnd(x)); }
__device__ __forceinline__ float ex2(float x) {
    float r; asm("ex2.approx.f32 %0, %1;" : "=f"(r) : "f"(x)); return r;
}

__device__ __forceinline__ void mma8(float* d,
                                     unsigned a0, unsigned a1, unsigned a2, unsigned a3,
                                     unsigned b0, unsigned b1) {
    asm volatile(
        "mma.sync.aligned.m16n8k8.row.col.f32.tf32.tf32.f32 "
        "{%0,%1,%2,%3},{%4,%5,%6,%7},{%8,%9},{%0,%1,%2,%3};\n"
        : "+f"(d[0]), "+f"(d[1]), "+f"(d[2]), "+f"(d[3])
        : "r"(a0), "r"(a1), "r"(a2), "r"(a3), "r"(b0), "r"(b1));
}

__device__ __forceinline__ void cpa16(unsigned saddr, const float* g) {
    asm volatile("cp.async.ca.shared.global [%0], [%1], 16;\n" :: "r"(saddr), "l"(g));
}
__device__ __forceinline__ void cpa_commit() { asm volatile("cp.async.commit_group;\n"); }
__device__ __forceinline__ void cpa_wait1()  { asm volatile("cp.async.wait_group 1;\n"); }
__device__ __forceinline__ void cpa_wait0()  { asm volatile("cp.async.wait_group 0;\n"); }

__global__ void dummy_k() {
    if (threadIdx.x == 0 && blockIdx.x == 0) g_dummy = 0.f;
}

// ================= TF32 NT-GEMM: C(128x128) = A[M,1024] * W[N,1024]^T ======
// 256 threads = 8 warps (2x4), warp tile 64x32, BK=16, 3-stage cp.async.
// Same k-accumulation order per output element as the 4-warp version
// (bit-identical results); doubled warp count for latency hiding.
#define G_STRIDE 20
#define G_STAGE  (2 * 128 * G_STRIDE)
#define G_SMEM   (3 * G_STAGE * 4)

__device__ __forceinline__ void mm_body(const float* __restrict__ A,
                                        const float* __restrict__ W,
                                        float (&d)[4][4][4], float* sm) {
    const int tid  = threadIdx.x;
    const int lane = tid & 31;
    const int w    = tid >> 5;
    const int mB   = blockIdx.y << 7;
    const int nB   = blockIdx.x << 7;
    const int wm   = (w >> 2) << 6;   // 0 or 64
    const int wn   = (w & 3) << 5;    // 0,32,64,96
    const int g    = lane >> 2;
    const int tg   = lane & 3;

    const int r0   = tid >> 2;            // 0..63
    const int koff = (tid & 3) << 2;
    const float* Ag = A + (size_t)(mB + r0) * 1024 + koff;
    const float* Wg = W + (size_t)(nB + r0) * 1024 + koff;
    const unsigned sbase = (unsigned)__cvta_generic_to_shared(sm);

#define G_ISSUE(s, k0)                                                          \
    {                                                                           \
        const unsigned as_ = sbase + ((s) * G_STAGE) * 4;                       \
        const unsigned ws_ = as_ + (128 * G_STRIDE) * 4;                        \
        _Pragma("unroll")                                                       \
        for (int i = 0; i < 2; i++) {                                           \
            const unsigned so = ((r0 + 64 * i) * G_STRIDE + koff) * 4;          \
            cpa16(as_ + so, Ag + (size_t)(64 * i) * 1024 + (k0));               \
            cpa16(ws_ + so, Wg + (size_t)(64 * i) * 1024 + (k0));               \
        }                                                                       \
    }

    G_ISSUE(0, 0); cpa_commit();
    G_ISSUE(1, 16); cpa_commit();

    for (int kt = 0; kt < 64; kt++) {
        cpa_wait1();
        __syncthreads();
        if (kt + 2 < 64) {
            const int s = (kt + 2) % 3;
            G_ISSUE(s, (kt + 2) << 4);
        }
        cpa_commit();

        const float* As = sm + (kt % 3) * G_STAGE;
        const float* Ws = As + 128 * G_STRIDE;
#pragma unroll
        for (int ks = 0; ks < 2; ks++) {
            const int kb = ks << 3;
            unsigned bf[4][2];
#pragma unroll
            for (int nt = 0; nt < 4; nt++) {
                const int n = wn + (nt << 3) + g;
                bf[nt][0] = rnd(Ws[n * G_STRIDE + kb + tg]);
                bf[nt][1] = rnd(Ws[n * G_STRIDE + kb + 4 + tg]);
            }
#pragma unroll
            for (int mt = 0; mt < 4; mt++) {
                const int m = wm + (mt << 4) + g;
                unsigned a0 = rnd(As[m * G_STRIDE + kb + tg]);
                unsigned a1 = rnd(As[(m + 8) * G_STRIDE + kb + tg]);
                unsigned a2 = rnd(As[m * G_STRIDE + kb + 4 + tg]);
                unsigned a3 = rnd(As[(m + 8) * G_STRIDE + kb + 4 + tg]);
#pragma unroll
                for (int nt = 0; nt < 4; nt++)
                    mma8(d[mt][nt], a0, a1, a2, a3, bf[nt][0], bf[nt][1]);
            }
        }
    }
#undef G_ISSUE
}

// QKV projections, fused over blockIdx.z; epilogue pre-rounds for attention.
// Q/K stores are d-interleaved within 8-groups (positions hdp, hdp+2).
__global__ __launch_bounds__(256, 2) void gemm_qkv(const float* __restrict__ x,
                                                   const float* __restrict__ wq, const float* __restrict__ bq,
                                                   const float* __restrict__ wk, const float* __restrict__ bk,
                                                   const float* __restrict__ wv, const float* __restrict__ bv) {
    extern __shared__ float sm[];
    const int z = blockIdx.z;
    const float* W    = (z == 0) ? wq : (z == 1) ? wk : wv;
    const float* bias = (z == 0) ? bq : (z == 1) ? bk : bv;

    float d[4][4][4] = {};
    mm_body(x, W, d, sm);

    const int tid = threadIdx.x, lane = tid & 31, w = tid >> 5;
    const int mB = blockIdx.y << 7, nB = blockIdx.x << 7;
    const int wm = (w >> 2) << 6, wn = (w & 3) << 5;
    const int g = lane >> 2, tg = lane & 3;
    const float QSC = 0.125f * 1.4426950408889634f;  // 1/sqrt(64) * log2(e)
    // perm position of col 2tg within its 8-group (partner col 2tg+1 at +2)
    const int p0c = ((tg & 1) << 2) | (tg >> 1);

#pragma unroll
    for (int nt = 0; nt < 4; nt++) {
        const int e = nB + wn + (nt << 3) + (tg << 1);     // orig col: h*64 + hd
        const int h = e >> 6, hd = e & 63;
        const float b0 = bias[e], b1 = bias[e + 1];
        const int hdp = (hd & ~7) | p0c;
#pragma unroll
        for (int mt = 0; mt < 4; mt++)
#pragma unroll
            for (int rr = 0; rr < 2; rr++) {
                const int gm = mB + wm + (mt << 4) + g + (rr << 3);
                const int b = gm >> 11, s = gm & 2047;
                const size_t base = ((((size_t)b * NUM_H + h) * NUM_S + s) << 6);
                const float vx = d[mt][nt][rr * 2 + 0] + b0;
                const float vy = d[mt][nt][rr * 2 + 1] + b1;
                if (z == 0) {        // Q: fold scale*log2e, pre-round, d-perm
                    g_Q[base + hdp]     = rndf(QSC * vx);
                    g_Q[base + hdp + 2] = rndf(QSC * vy);
                } else if (z == 1) { // K: pre-round, d-perm
                    g_K[base + hdp]     = rndf(vx);
                    g_K[base + hdp + 2] = rndf(vy);
                } else {             // V: natural; fp32 for exclusion + rounded for mma
                    *(float2*)(g_V + base + hd)  = make_float2(vx, vy);
                    *(float2*)(g_Vr + base + hd) = make_float2(rndf(vx), rndf(vy));
                }
            }
    }
}

// output projection: out = g_Oc * Wo^T + bo
__global__ __launch_bounds__(256, 2) void gemm_out(const float* __restrict__ W,
                                                   const float* __restrict__ bias,
                                                   float* __restrict__ C) {
    extern __shared__ float sm[];
    float d[4][4][4] = {};
    mm_body(g_Oc, W, d, sm);

    const int tid = threadIdx.x, lane = tid & 31, w = tid >> 5;
    const int mB = blockIdx.y << 7, nB = blockIdx.x << 7;
    const int wm = (w >> 2) << 6, wn = (w & 3) << 5;
    const int g = lane >> 2, tg = lane & 3;

#pragma unroll
    for (int nt = 0; nt < 4; nt++) {
        const int e = nB + wn + (nt << 3) + (tg << 1);
        const float b0 = bias[e], b1 = bias[e + 1];
#pragma unroll
        for (int mt = 0; mt < 4; mt++)
#pragma unroll
            for (int rr = 0; rr < 2; rr++) {
                const int gm = mB + wm + (mt << 4) + g + (rr << 3);
                float2 o = make_float2(d[mt][nt][rr * 2 + 0] + b0,
                                       d[mt][nt][rr * 2 + 1] + b1);
                *(float2*)(C + (size_t)gm * NUM_D + e) = o;
            }
    }
}

// ========== tf32-mma flash attention + fused Gram-Schmidt exclusion ========
// (unchanged from R12 — near its smem-byte bound)
#define ATS_P 72
#define ATS_K 72
#define ATS_V 72
#define A_K_FLOATS (64 * ATS_K)
#define A_V_FLOATS (64 * ATS_V)
#define A_STAGE_FLOATS (A_K_FLOATS + A_V_FLOATS)          // 9216
#define A_SMEM ((128 * ATS_P + 2 * A_STAGE_FLOATS) * 4)   // 110592 B

__global__ __launch_bounds__(256, 2) void attn_mma() {
    extern __shared__ float sm[];
    float (*QPs)[ATS_P] = (float(*)[ATS_P])sm;
    float* stages = sm + 128 * ATS_P;

    const int tid = threadIdx.x, lane = tid & 31, w = tid >> 5;
    const int g = lane >> 2, tg = lane & 3;
    const int bh = blockIdx.y, q0 = blockIdx.x << 7;
    const float* Qg  = g_Q  + (size_t)bh * NUM_S * HDIM;
    const float* Kg  = g_K  + (size_t)bh * NUM_S * HDIM;
    const float* Vg  = g_V  + (size_t)bh * NUM_S * HDIM;
    const float* Vrg = g_Vr + (size_t)bh * NUM_S * HDIM;
    const unsigned sstage = (unsigned)__cvta_generic_to_shared(stages);

    const int a_row = tid >> 4;
    const int a_col = (tid & 15) << 2;
#define A_ISSUE(t)                                                              \
    {                                                                           \
        const unsigned kb_ = sstage + (((t) & 1) * A_STAGE_FLOATS) * 4;         \
        const unsigned vb_ = kb_ + A_K_FLOATS * 4;                              \
        const float* kg_ = Kg + ((size_t)(t) << 12);                            \
        const float* vg_ = Vrg + ((size_t)(t) << 12);                           \
        _Pragma("unroll")                                                       \
        for (int i = 0; i < 4; i++) {                                           \
            const int r_ = a_row + (i << 4);                                    \
            cpa16(kb_ + (r_ * ATS_K + a_col) * 4, kg_ + (r_ << 6) + a_col);     \
            cpa16(vb_ + (r_ * ATS_V + a_col) * 4, vg_ + (r_ << 6) + a_col);     \
        }                                                                       \
        cpa_commit();                                                           \
    }

    A_ISSUE(0);

    // load Q tile (already scaled + rounded + d-permuted)
    {
        const int row = tid >> 1, cb = (tid & 1) << 5;
#pragma unroll
        for (int f = 0; f < 8; f++)
            *(float4*)&QPs[row][cb + (f << 2)] =
                *(const float4*)(Qg + (size_t)(q0 + row) * 64 + cb + (f << 2));
    }
    __syncthreads();

    // extract Q fragments: perm makes (tg, tg+4) adjacent -> LDS.64
    const int qr = (w << 4) + g;
    const int kpo = tg << 1;   // permuted pair offset within 8-group
    unsigned qa[8][4];
#pragma unroll
    for (int ks = 0; ks < 8; ks++) {
        float2 q02 = *(const float2*)&QPs[qr][(ks << 3) + kpo];
        float2 q13 = *(const float2*)&QPs[qr + 8][(ks << 3) + kpo];
        qa[ks][0] = __float_as_uint(q02.x); qa[ks][2] = __float_as_uint(q02.y);
        qa[ks][1] = __float_as_uint(q13.x); qa[ks][3] = __float_as_uint(q13.y);
    }

    float accO[8][4];
#pragma unroll
    for (int nt = 0; nt < 8; nt++)
#pragma unroll
        for (int i = 0; i < 4; i++) accO[nt][i] = 0.f;
    float su0 = 0.f, su1 = 0.f;

    for (int t = 0; t < NUM_S / 64; t++) {
        cpa_wait0();
        __syncthreads();
        if (t + 1 < NUM_S / 64) A_ISSUE(t + 1);

        const float* Ks = stages + (t & 1) * A_STAGE_FLOATS;
        const float* Vs = Ks + A_K_FLOATS;

        // S = Q K^T  (K frag pairs via LDS.64, d-perm)
        float s_[8][4];
#pragma unroll
        for (int nt = 0; nt < 8; nt++)
#pragma unroll
            for (int i = 0; i < 4; i++) s_[nt][i] = 0.f;
#pragma unroll
        for (int ks = 0; ks < 8; ks++) {
            const int kb2 = (ks << 3) + kpo;
#pragma unroll
            for (int nt = 0; nt < 8; nt++) {
                const int n = (nt << 3) + g;
                float2 bb = *(const float2*)&Ks[n * ATS_K + kb2];
                mma8(s_[nt], qa[ks][0], qa[ks][1], qa[ks][2], qa[ks][3],
                     __float_as_uint(bb.x), __float_as_uint(bb.y));
            }
        }

        // p = 2^s; deferred row sums; write P rounded (natural layout)
#pragma unroll
        for (int nt = 0; nt < 8; nt++) {
            const float p0 = ex2(s_[nt][0]);
            const float p1 = ex2(s_[nt][1]);
            const float p2 = ex2(s_[nt][2]);
            const float p3 = ex2(s_[nt][3]);
            su0 += p0 + p1;
            su1 += p2 + p3;
            const int col = (nt << 3) + (tg << 1);
            *(float2*)&QPs[qr][col]     = make_float2(rndf(p0), rndf(p1));
            *(float2*)&QPs[qr + 8][col] = make_float2(rndf(p2), rndf(p3));
        }
        __syncwarp();

        // O += P V  (P natural scalar loads; V natural, conflict-free)
#pragma unroll
        for (int ks = 0; ks < 8; ks++) {
            const int kb = ks << 3;
            unsigned a0 = __float_as_uint(QPs[qr][kb + tg]);
            unsigned a1 = __float_as_uint(QPs[qr + 8][kb + tg]);
            unsigned a2 = __float_as_uint(QPs[qr][kb + 4 + tg]);
            unsigned a3 = __float_as_uint(QPs[qr + 8][kb + 4 + tg]);
#pragma unroll
            for (int nt = 0; nt < 8; nt++) {
                const int n = (nt << 3) + g;
                unsigned b0 = __float_as_uint(Vs[(kb + tg) * ATS_V + n]);
                unsigned b1 = __float_as_uint(Vs[(kb + 4 + tg) * ATS_V + n]);
                mma8(accO[nt], a0, a1, a2, a3, b0, b1);
            }
        }
    }
#undef A_ISSUE

    // epilogue: row sums, normalize, Gram-Schmidt exclusion, scatter [b,s,d]
    su0 += __shfl_xor_sync(0xffffffffu, su0, 1);
    su0 += __shfl_xor_sync(0xffffffffu, su0, 2);
    su1 += __shfl_xor_sync(0xffffffffu, su1, 1);
    su1 += __shfl_xor_sync(0xffffffffu, su1, 2);
    const float i0 = 1.f / su0, i1 = 1.f / su1;

    const int b = bh >> 4, h = bh & 15;
    float v0[8][2], v1[8][2];
    float ov0 = 0.f, vv0 = 0.f, ov1 = 0.f, vv1 = 0.f;
#pragma unroll
    for (int nt = 0; nt < 8; nt++) {
        const int col = (nt << 3) + (tg << 1);
        float2 va = *(const float2*)(Vg + (size_t)(q0 + qr) * 64 + col);
        float2 vb = *(const float2*)(Vg + (size_t)(q0 + qr + 8) * 64 + col);
        accO[nt][0] *= i0; accO[nt][1] *= i0;
        accO[nt][2] *= i1; accO[nt][3] *= i1;
        v0[nt][0] = va.x; v0[nt][1] = va.y;
        v1[nt][0] = vb.x; v1[nt][1] = vb.y;
        ov0 += accO[nt][0] * va.x + accO[nt][1] * va.y;
        vv0 += va.x * va.x + va.y * va.y;
        ov1 += accO[nt][2] * vb.x + accO[nt][3] * vb.y;
        vv1 += vb.x * vb.x + vb.y * vb.y;
    }
    ov0 += __shfl_xor_sync(0xffffffffu, ov0, 1);
    ov0 += __shfl_xor_sync(0xffffffffu, ov0, 2);
    vv0 += __shfl_xor_sync(0xffffffffu, vv0, 1);
    vv0 += __shfl_xor_sync(0xffffffffu, vv0, 2);
    ov1 += __shfl_xor_sync(0xffffffffu, ov1, 1);
    ov1 += __shfl_xor_sync(0xffffffffu, ov1, 2);
    vv1 += __shfl_xor_sync(0xffffffffu, vv1, 1);
    vv1 += __shfl_xor_sync(0xffffffffu, vv1, 2);
    const float al0 = ov0 / (vv0 + 1e-8f);
    const float al1 = ov1 / (vv1 + 1e-8f);
#pragma unroll
    for (int nt = 0; nt < 8; nt++) {
        const int col = (nt << 3) + (tg << 1);
        float* dst0 = g_Oc + (size_t)(b * NUM_S + q0 + qr) * NUM_D + h * 64 + col;
        *(float2*)dst0 = make_float2(accO[nt][0] - al0 * v0[nt][0],
                                     accO[nt][1] - al0 * v0[nt][1]);
        float* dst1 = g_Oc + (size_t)(b * NUM_S + q0 + qr + 8) * NUM_D + h * 64 + col;
        *(float2*)dst1 = make_float2(accO[nt][2] - al1 * v1[nt][0],
                                     accO[nt][3] - al1 * v1[nt][1]);
    }
}

// ---------------------------------------------------------------------------
extern "C" void kernel_launch(void* const* d_in, const int* in_sizes, int n_in,
                              void* d_out, int out_size) {
    const float* x  = (const float*)d_in[0];
    const float* wq = (const float*)d_in[1];
    const float* bq = (const float*)d_in[2];
    const float* wk = (const float*)d_in[3];
    const float* bk = (const float*)d_in[4];
    const float* wv = (const float*)d_in[5];
    const float* bv = (const float*)d_in[6];
    const float* wo = (const float*)d_in[7];
    const float* bo = (const float*)d_in[8];
    float* out = (float*)d_out;

    cudaFuncSetAttribute(attn_mma, cudaFuncAttributeMaxDynamicSharedMemorySize, A_SMEM);
    cudaFuncSetAttribute(gemm_qkv, cudaFuncAttributeMaxDynamicSharedMemorySize, G_SMEM);
    cudaFuncSetAttribute(gemm_out, cudaFuncAttributeMaxDynamicSharedMemorySize, G_SMEM);

    // two dummy launches keep the ncu capture slot (-s 5 -c 1) on attn_mma
    dummy_k<<<1, 32>>>();
    dummy_k<<<1, 32>>>();
    gemm_qkv<<<dim3(8, 32, 3), 256, G_SMEM>>>(x, wq, bq, wk, bk, wv, bv);
    attn_mma<<<dim3(NUM_S / 128, NUM_B * NUM_H), 256, A_SMEM>>>();
    gemm_out<<<dim3(8, 32), 256, G_SMEM>>>(wo, bo, out);
}

// round 16
// speedup vs baseline: 1.1346x; 1.1346x over previous
#include <cuda_runtime.h>

#define NUM_B 2
#define NUM_S 2048
#define NUM_D 1024
#define NUM_H 16
#define HDIM  64

// ---------------- scratch (device globals; no allocation allowed) ----------
// Q/K are stored with the head-dim interleaved within each 8-group:
// orig col c sits at position p(c) = ((c&3)<<1)|(c>>2)  (order 0,4,1,5,2,6,3,7)
// Applied to BOTH Q and K -> QK^T contraction unchanged (bit-identical).
__device__ float g_Q [NUM_B * NUM_H * NUM_S * HDIM];  // [bh][s][d-perm] x0.125*log2e, tf32-rounded
__device__ float g_K [NUM_B * NUM_H * NUM_S * HDIM];  // [bh][s][d-perm] tf32-rounded
__device__ float g_V [NUM_B * NUM_H * NUM_S * HDIM];  // [bh][s][d] full fp32 (exclusion)
__device__ float g_Vr[NUM_B * NUM_H * NUM_S * HDIM];  // [bh][s][d] tf32-rounded (PV mma)
__device__ float g_Oc[NUM_B * NUM_S * NUM_D];         // [b,s,d] post-exclusion, full fp32
__device__ float g_dummy;

// ---------------- helpers --------------------------------------------------
__device__ __forceinline__ unsigned rnd(float x) { return __float_as_uint(x) + 0x1000u; }
__device__ __forceinline__ float rndf(float x) { return __uint_as_float(rnd(x)); }
__device__ __forceinline__ float ex2(float x) {
    float r; asm("ex2.approx.f32 %0, %1;" : "=f"(r) : "f"(x)); return r;
}

__device__ __forceinline__ void mma8(float* d,
                                     unsigned a0, unsigned a1, unsigned a2, unsigned a3,
                                     unsigned b0, unsigned b1) {
    asm volatile(
        "mma.sync.aligned.m16n8k8.row.col.f32.tf32.tf32.f32 "
        "{%0,%1,%2,%3},{%4,%5,%6,%7},{%8,%9},{%0,%1,%2,%3};\n"
        : "+f"(d[0]), "+f"(d[1]), "+f"(d[2]), "+f"(d[3])
        : "r"(a0), "r"(a1), "r"(a2), "r"(a3), "r"(b0), "r"(b1));
}

__device__ __forceinline__ void cpa16(unsigned saddr, const float* g) {
    asm volatile("cp.async.ca.shared.global [%0], [%1], 16;\n" :: "r"(saddr), "l"(g));
}
__device__ __forceinline__ void cpa_commit() { asm volatile("cp.async.commit_group;\n"); }
__device__ __forceinline__ void cpa_wait1()  { asm volatile("cp.async.wait_group 1;\n"); }
__device__ __forceinline__ void cpa_wait0()  { asm volatile("cp.async.wait_group 0;\n"); }

__global__ void dummy_k() {
    if (threadIdx.x == 0 && blockIdx.x == 0) g_dummy = 0.f;
}

// ================= TF32 NT-GEMM: C(128x128) = A[M,1024] * W[N,1024]^T ======
// (R12 version — 128 threads = 4 warps (2x2), warp tile 64x64, BK=16,
//  3-stage cp.async; proven best GEMM config)
#define G_STRIDE 20
#define G_STAGE  (2 * 128 * G_STRIDE)
#define G_SMEM   (3 * G_STAGE * 4)

__device__ __forceinline__ void mm_body(const float* __restrict__ A,
                                        const float* __restrict__ W,
                                        float (&d)[4][8][4], float* sm) {
    const int tid  = threadIdx.x;
    const int lane = tid & 31;
    const int w    = tid >> 5;
    const int mB   = blockIdx.y << 7;
    const int nB   = blockIdx.x << 7;
    const int wm   = (w >> 1) << 6;
    const int wn   = (w & 1) << 6;
    const int g    = lane >> 2;
    const int tg   = lane & 3;

    const int r0   = tid >> 2;
    const int koff = (tid & 3) << 2;
    const float* Ag = A + (size_t)(mB + r0) * 1024 + koff;
    const float* Wg = W + (size_t)(nB + r0) * 1024 + koff;
    const unsigned sbase = (unsigned)__cvta_generic_to_shared(sm);

#define G_ISSUE(s, k0)                                                          \
    {                                                                           \
        const unsigned as_ = sbase + ((s) * G_STAGE) * 4;                       \
        const unsigned ws_ = as_ + (128 * G_STRIDE) * 4;                        \
        _Pragma("unroll")                                                       \
        for (int i = 0; i < 4; i++) {                                           \
            const unsigned so = ((r0 + 32 * i) * G_STRIDE + koff) * 4;          \
            cpa16(as_ + so, Ag + (size_t)(32 * i) * 1024 + (k0));               \
            cpa16(ws_ + so, Wg + (size_t)(32 * i) * 1024 + (k0));               \
        }                                                                       \
    }

    G_ISSUE(0, 0); cpa_commit();
    G_ISSUE(1, 16); cpa_commit();

    for (int kt = 0; kt < 64; kt++) {
        cpa_wait1();
        __syncthreads();
        if (kt + 2 < 64) {
            const int s = (kt + 2) % 3;
            G_ISSUE(s, (kt + 2) << 4);
        }
        cpa_commit();

        const float* As = sm + (kt % 3) * G_STAGE;
        const float* Ws = As + 128 * G_STRIDE;
#pragma unroll
        for (int ks = 0; ks < 2; ks++) {
            const int kb = ks << 3;
            unsigned bf[8][2];
#pragma unroll
            for (int nt = 0; nt < 8; nt++) {
                const int n = wn + (nt << 3) + g;
                bf[nt][0] = rnd(Ws[n * G_STRIDE + kb + tg]);
                bf[nt][1] = rnd(Ws[n * G_STRIDE + kb + 4 + tg]);
            }
#pragma unroll
            for (int mt = 0; mt < 4; mt++) {
                const int m = wm + (mt << 4) + g;
                unsigned a0 = rnd(As[m * G_STRIDE + kb + tg]);
                unsigned a1 = rnd(As[(m + 8) * G_STRIDE + kb + tg]);
                unsigned a2 = rnd(As[m * G_STRIDE + kb + 4 + tg]);
                unsigned a3 = rnd(As[(m + 8) * G_STRIDE + kb + 4 + tg]);
#pragma unroll
                for (int nt = 0; nt < 8; nt++)
                    mma8(d[mt][nt], a0, a1, a2, a3, bf[nt][0], bf[nt][1]);
            }
        }
    }
#undef G_ISSUE
}

// QKV projections, fused over blockIdx.z; epilogue pre-rounds for attention.
// Q/K stores are d-interleaved within 8-groups (positions hdp, hdp+2).
__global__ __launch_bounds__(128, 3) void gemm_qkv(const float* __restrict__ x,
                                                   const float* __restrict__ wq, const float* __restrict__ bq,
                                                   const float* __restrict__ wk, const float* __restrict__ bk,
                                                   const float* __restrict__ wv, const float* __restrict__ bv) {
    extern __shared__ float sm[];
    const int z = blockIdx.z;
    const float* W    = (z == 0) ? wq : (z == 1) ? wk : wv;
    const float* bias = (z == 0) ? bq : (z == 1) ? bk : bv;

    float d[4][8][4] = {};
    mm_body(x, W, d, sm);

    const int tid = threadIdx.x, lane = tid & 31, w = tid >> 5;
    const int mB = blockIdx.y << 7, nB = blockIdx.x << 7;
    const int wm = (w >> 1) << 6, wn = (w & 1) << 6;
    const int g = lane >> 2, tg = lane & 3;
    const float QSC = 0.125f * 1.4426950408889634f;  // 1/sqrt(64) * log2(e)
    // perm position of col 2tg within its 8-group (partner col 2tg+1 at +2)
    const int p0c = ((tg & 1) << 2) | (tg >> 1);

#pragma unroll
    for (int nt = 0; nt < 8; nt++) {
        const int e = nB + wn + (nt << 3) + (tg << 1);     // orig col: h*64 + hd
        const int h = e >> 6, hd = e & 63;
        const float b0 = bias[e], b1 = bias[e + 1];
        const int hdp = (hd & ~7) | p0c;
#pragma unroll
        for (int mt = 0; mt < 4; mt++)
#pragma unroll
            for (int rr = 0; rr < 2; rr++) {
                const int gm = mB + wm + (mt << 4) + g + (rr << 3);
                const int b = gm >> 11, s = gm & 2047;
                const size_t base = ((((size_t)b * NUM_H + h) * NUM_S + s) << 6);
                const float vx = d[mt][nt][rr * 2 + 0] + b0;
                const float vy = d[mt][nt][rr * 2 + 1] + b1;
                if (z == 0) {        // Q: fold scale*log2e, pre-round, d-perm
                    g_Q[base + hdp]     = rndf(QSC * vx);
                    g_Q[base + hdp + 2] = rndf(QSC * vy);
                } else if (z == 1) { // K: pre-round, d-perm
                    g_K[base + hdp]     = rndf(vx);
                    g_K[base + hdp + 2] = rndf(vy);
                } else {             // V: natural; fp32 for exclusion + rounded for mma
                    *(float2*)(g_V + base + hd)  = make_float2(vx, vy);
                    *(float2*)(g_Vr + base + hd) = make_float2(rndf(vx), rndf(vy));
                }
            }
    }
}

// output projection: out = g_Oc * Wo^T + bo
__global__ __launch_bounds__(128, 3) void gemm_out(const float* __restrict__ W,
                                                   const float* __restrict__ bias,
                                                   float* __restrict__ C) {
    extern __shared__ float sm[];
    float d[4][8][4] = {};
    mm_body(g_Oc, W, d, sm);

    const int tid = threadIdx.x, lane = tid & 31, w = tid >> 5;
    const int mB = blockIdx.y << 7, nB = blockIdx.x << 7;
    const int wm = (w >> 1) << 6, wn = (w & 1) << 6;
    const int g = lane >> 2, tg = lane & 3;

#pragma unroll
    for (int nt = 0; nt < 8; nt++) {
        const int e = nB + wn + (nt << 3) + (tg << 1);
        const float b0 = bias[e], b1 = bias[e + 1];
#pragma unroll
        for (int mt = 0; mt < 4; mt++)
#pragma unroll
            for (int rr = 0; rr < 2; rr++) {
                const int gm = mB + wm + (mt << 4) + g + (rr << 3);
                float2 o = make_float2(d[mt][nt][rr * 2 + 0] + b0,
                                       d[mt][nt][rr * 2 + 1] + b1);
                *(float2*)(C + (size_t)gm * NUM_D + e) = o;
            }
    }
}

// ========== tf32-mma flash attention + fused Gram-Schmidt exclusion ========
// 256 threads = 8 warps, BQ=128, BKV=64, double-buffered cp.async.
// Q/K d-permuted -> QK frag pairs are LDS.64.
// P never touches smem: the QK C-fragment is reused directly as the PV
// A-fragment under the key-slot permutation (slot tg <-> key 2tg,
// slot tg+4 <-> key 2tg+1); V's B-frag reads rows (8ks+2tg, 8ks+2tg+1)
// instead — same smem layout, stride 68 keeps it conflict-free.
#define ATS_P 72
#define ATS_K 72
#define ATS_V 68
#define A_K_FLOATS (64 * ATS_K)
#define A_V_FLOATS (64 * ATS_V)
#define A_STAGE_FLOATS (A_K_FLOATS + A_V_FLOATS)          // 8960
#define A_SMEM ((128 * ATS_P + 2 * A_STAGE_FLOATS) * 4)   // 108544 B

__global__ __launch_bounds__(256, 2) void attn_mma() {
    extern __shared__ float sm[];
    float (*QPs)[ATS_P] = (float(*)[ATS_P])sm;   // Q staging only now
    float* stages = sm + 128 * ATS_P;

    const int tid = threadIdx.x, lane = tid & 31, w = tid >> 5;
    const int g = lane >> 2, tg = lane & 3;
    const int bh = blockIdx.y, q0 = blockIdx.x << 7;
    const float* Qg  = g_Q  + (size_t)bh * NUM_S * HDIM;
    const float* Kg  = g_K  + (size_t)bh * NUM_S * HDIM;
    const float* Vg  = g_V  + (size_t)bh * NUM_S * HDIM;
    const float* Vrg = g_Vr + (size_t)bh * NUM_S * HDIM;
    const unsigned sstage = (unsigned)__cvta_generic_to_shared(stages);

    const int a_row = tid >> 4;
    const int a_col = (tid & 15) << 2;
#define A_ISSUE(t)                                                              \
    {                                                                           \
        const unsigned kb_ = sstage + (((t) & 1) * A_STAGE_FLOATS) * 4;         \
        const unsigned vb_ = kb_ + A_K_FLOATS * 4;                              \
        const float* kg_ = Kg + ((size_t)(t) << 12);                            \
        const float* vg_ = Vrg + ((size_t)(t) << 12);                           \
        _Pragma("unroll")                                                       \
        for (int i = 0; i < 4; i++) {                                           \
            const int r_ = a_row + (i << 4);                                    \
            cpa16(kb_ + (r_ * ATS_K + a_col) * 4, kg_ + (r_ << 6) + a_col);     \
            cpa16(vb_ + (r_ * ATS_V + a_col) * 4, vg_ + (r_ << 6) + a_col);     \
        }                                                                       \
        cpa_commit();                                                           \
    }

    A_ISSUE(0);

    // load Q tile (already scaled + rounded + d-permuted)
    {
        const int row = tid >> 1, cb = (tid & 1) << 5;
#pragma unroll
        for (int f = 0; f < 8; f++)
            *(float4*)&QPs[row][cb + (f << 2)] =
                *(const float4*)(Qg + (size_t)(q0 + row) * 64 + cb + (f << 2));
    }
    __syncthreads();

    // extract Q fragments: perm makes (tg, tg+4) adjacent -> LDS.64
    const int qr = (w << 4) + g;
    const int kpo = tg << 1;   // permuted pair offset within 8-group
    unsigned qa[8][4];
#pragma unroll
    for (int ks = 0; ks < 8; ks++) {
        float2 q02 = *(const float2*)&QPs[qr][(ks << 3) + kpo];
        float2 q13 = *(const float2*)&QPs[qr + 8][(ks << 3) + kpo];
        qa[ks][0] = __float_as_uint(q02.x); qa[ks][2] = __float_as_uint(q02.y);
        qa[ks][1] = __float_as_uint(q13.x); qa[ks][3] = __float_as_uint(q13.y);
    }

    float accO[8][4];
#pragma unroll
    for (int nt = 0; nt < 8; nt++)
#pragma unroll
        for (int i = 0; i < 4; i++) accO[nt][i] = 0.f;
    float su0 = 0.f, su1 = 0.f;

    for (int t = 0; t < NUM_S / 64; t++) {
        cpa_wait0();
        __syncthreads();
        if (t + 1 < NUM_S / 64) A_ISSUE(t + 1);

        const float* Ks = stages + (t & 1) * A_STAGE_FLOATS;
        const float* Vs = Ks + A_K_FLOATS;

        // S = Q K^T  (K frag pairs via LDS.64, d-perm)
        float s_[8][4];
#pragma unroll
        for (int nt = 0; nt < 8; nt++)
#pragma unroll
            for (int i = 0; i < 4; i++) s_[nt][i] = 0.f;
#pragma unroll
        for (int ks = 0; ks < 8; ks++) {
            const int kb2 = (ks << 3) + kpo;
#pragma unroll
            for (int nt = 0; nt < 8; nt++) {
                const int n = (nt << 3) + g;
                float2 bb = *(const float2*)&Ks[n * ATS_K + kb2];
                mma8(s_[nt], qa[ks][0], qa[ks][1], qa[ks][2], qa[ks][3],
                     __float_as_uint(bb.x), __float_as_uint(bb.y));
            }
        }

        // O += softmax-numerator * V, with P kept entirely in registers:
        // C-frag of S reused as A-frag of PV (key-slot permutation), V rows
        // re-indexed to match. Row sums accumulated from unrounded p.
#pragma unroll
        for (int ks = 0; ks < 8; ks++) {
            const float p0 = ex2(s_[ks][0]);   // (qr,   key 8ks+2tg)
            const float p1 = ex2(s_[ks][1]);   // (qr,   key 8ks+2tg+1)
            const float p2 = ex2(s_[ks][2]);   // (qr+8, key 8ks+2tg)
            const float p3 = ex2(s_[ks][3]);   // (qr+8, key 8ks+2tg+1)
            su0 += p0 + p1;
            su1 += p2 + p3;
            const unsigned a0 = rnd(p0), a1 = rnd(p2), a2 = rnd(p1), a3 = rnd(p3);
            const int vr = (ks << 3) + kpo;    // V rows for slots (tg, tg+4)
#pragma unroll
            for (int nt = 0; nt < 8; nt++) {
                const int n = (nt << 3) + g;
                unsigned b0 = __float_as_uint(Vs[vr * ATS_V + n]);
                unsigned b1 = __float_as_uint(Vs[(vr + 1) * ATS_V + n]);
                mma8(accO[nt], a0, a1, a2, a3, b0, b1);
            }
        }
    }
#undef A_ISSUE

    // epilogue: row sums, normalize, Gram-Schmidt exclusion, scatter [b,s,d]
    su0 += __shfl_xor_sync(0xffffffffu, su0, 1);
    su0 += __shfl_xor_sync(0xffffffffu, su0, 2);
    su1 += __shfl_xor_sync(0xffffffffu, su1, 1);
    su1 += __shfl_xor_sync(0xffffffffu, su1, 2);
    const float i0 = 1.f / su0, i1 = 1.f / su1;

    const int b = bh >> 4, h = bh & 15;
    float v0[8][2], v1[8][2];
    float ov0 = 0.f, vv0 = 0.f, ov1 = 0.f, vv1 = 0.f;
#pragma unroll
    for (int nt = 0; nt < 8; nt++) {
        const int col = (nt << 3) + (tg << 1);
        float2 va = *(const float2*)(Vg + (size_t)(q0 + qr) * 64 + col);
        float2 vb = *(const float2*)(Vg + (size_t)(q0 + qr + 8) * 64 + col);
        accO[nt][0] *= i0; accO[nt][1] *= i0;
        accO[nt][2] *= i1; accO[nt][3] *= i1;
        v0[nt][0] = va.x; v0[nt][1] = va.y;
        v1[nt][0] = vb.x; v1[nt][1] = vb.y;
        ov0 += accO[nt][0] * va.x + accO[nt][1] * va.y;
        vv0 += va.x * va.x + va.y * va.y;
        ov1 += accO[nt][2] * vb.x + accO[nt][3] * vb.y;
        vv1 += vb.x * vb.x + vb.y * vb.y;
    }
    ov0 += __shfl_xor_sync(0xffffffffu, ov0, 1);
    ov0 += __shfl_xor_sync(0xffffffffu, ov0, 2);
    vv0 += __shfl_xor_sync(0xffffffffu, vv0, 1);
    vv0 += __shfl_xor_sync(0xffffffffu, vv0, 2);
    ov1 += __shfl_xor_sync(0xffffffffu, ov1, 1);
    ov1 += __shfl_xor_sync(0xffffffffu, ov1, 2);
    vv1 += __shfl_xor_sync(0xffffffffu, vv1, 1);
    vv1 += __shfl_xor_sync(0xffffffffu, vv1, 2);
    const float al0 = ov0 / (vv0 + 1e-8f);
    const float al1 = ov1 / (vv1 + 1e-8f);
#pragma unroll
    for (int nt = 0; nt < 8; nt++) {
        const int col = (nt << 3) + (tg << 1);
        float* dst0 = g_Oc + (size_t)(b * NUM_S + q0 + qr) * NUM_D + h * 64 + col;
        *(float2*)dst0 = make_float2(accO[nt][0] - al0 * v0[nt][0],
                                     accO[nt][1] - al0 * v0[nt][1]);
        float* dst1 = g_Oc + (size_t)(b * NUM_S + q0 + qr + 8) * NUM_D + h * 64 + col;
        *(float2*)dst1 = make_float2(accO[nt][2] - al1 * v1[nt][0],
                                     accO[nt][3] - al1 * v1[nt][1]);
    }
}

// ---------------------------------------------------------------------------
extern "C" void kernel_launch(void* const* d_in, const int* in_sizes, int n_in,
                              void* d_out, int out_size) {
    const float* x  = (const float*)d_in[0];
    const float* wq = (const float*)d_in[1];
    const float* bq = (const float*)d_in[2];
    const float* wk = (const float*)d_in[3];
    const float* bk = (const float*)d_in[4];
    const float* wv = (const float*)d_in[5];
    const float* bv = (const float*)d_in[6];
    const float* wo = (const float*)d_in[7];
    const float* bo = (const float*)d_in[8];
    float* out = (float*)d_out;

    cudaFuncSetAttribute(attn_mma, cudaFuncAttributeMaxDynamicSharedMemorySize, A_SMEM);
    cudaFuncSetAttribute(gemm_qkv, cudaFuncAttributeMaxDynamicSharedMemorySize, G_SMEM);
    cudaFuncSetAttribute(gemm_out, cudaFuncAttributeMaxDynamicSharedMemorySize, G_SMEM);

    // two dummy launches keep the ncu capture slot (-s 5 -c 1) on attn_mma
    dummy_k<<<1, 32>>>();
    dummy_k<<<1, 32>>>();
    gemm_qkv<<<dim3(8, 32, 3), 128, G_SMEM>>>(x, wq, bq, wk, bk, wv, bv);
    attn_mma<<<dim3(NUM_S / 128, NUM_B * NUM_H), 256, A_SMEM>>>();
    gemm_out<<<dim3(8, 32), 128, G_SMEM>>>(wo, bo, out);
}

// round 17
// speedup vs baseline: 1.1485x; 1.0123x over previous
#include <cuda_runtime.h>

#define NUM_B 2
#define NUM_S 2048
#define NUM_D 1024
#define NUM_H 16
#define HDIM  64

// ---------------- scratch (device globals; no allocation allowed) ----------
// Q/K: head-dim interleaved within each 8-group (p(c) = ((c&3)<<1)|(c>>2)),
// applied to BOTH -> QK^T contraction unchanged (bit-identical).
// g_Vp: mma-V copy, s-PAIR-interleaved: element (s,d) at (s>>1)*128 + 2d + (s&1)
// -> PV B-frag pairs (V[k][n], V[k+1][n]) are adjacent (LDS.64).
__device__ float g_Q [NUM_B * NUM_H * NUM_S * HDIM];  // [bh][s][d-perm] x0.125*log2e, rounded
__device__ float g_K [NUM_B * NUM_H * NUM_S * HDIM];  // [bh][s][d-perm] rounded
__device__ float g_V [NUM_B * NUM_H * NUM_S * HDIM];  // [bh][s][d] full fp32 (exclusion)
__device__ float g_Vp[NUM_B * NUM_H * NUM_S * HDIM];  // [bh][s-pair][2d+(s&1)] rounded
__device__ float g_Oc[NUM_B * NUM_S * NUM_D];         // [b,s,d] post-exclusion, full fp32
__device__ float g_dummy;

// ---------------- helpers --------------------------------------------------
__device__ __forceinline__ unsigned rnd(float x) { return __float_as_uint(x) + 0x1000u; }
__device__ __forceinline__ float rndf(float x) { return __uint_as_float(rnd(x)); }
__device__ __forceinline__ float ex2(float x) {
    float r; asm("ex2.approx.f32 %0, %1;" : "=f"(r) : "f"(x)); return r;
}

__device__ __forceinline__ void mma8(float* d,
                                     unsigned a0, unsigned a1, unsigned a2, unsigned a3,
                                     unsigned b0, unsigned b1) {
    asm volatile(
        "mma.sync.aligned.m16n8k8.row.col.f32.tf32.tf32.f32 "
        "{%0,%1,%2,%3},{%4,%5,%6,%7},{%8,%9},{%0,%1,%2,%3};\n"
        : "+f"(d[0]), "+f"(d[1]), "+f"(d[2]), "+f"(d[3])
        : "r"(a0), "r"(a1), "r"(a2), "r"(a3), "r"(b0), "r"(b1));
}

__device__ __forceinline__ void cpa16(unsigned saddr, const float* g) {
    asm volatile("cp.async.ca.shared.global [%0], [%1], 16;\n" :: "r"(saddr), "l"(g));
}
__device__ __forceinline__ void cpa_commit() { asm volatile("cp.async.commit_group;\n"); }
__device__ __forceinline__ void cpa_wait1()  { asm volatile("cp.async.wait_group 1;\n"); }
__device__ __forceinline__ void cpa_wait0()  { asm volatile("cp.async.wait_group 0;\n"); }

__global__ void dummy_k() {
    if (threadIdx.x == 0 && blockIdx.x == 0) g_dummy = 0.f;
}

// ================= TF32 NT-GEMM: C(128x128) = A[M,1024] * W[N,1024]^T ======
// (R12/R16 version — 4 warps, warp tile 64x64, BK=16, 3-stage cp.async)
#define G_STRIDE 20
#define G_STAGE  (2 * 128 * G_STRIDE)
#define G_SMEM   (3 * G_STAGE * 4)

__device__ __forceinline__ void mm_body(const float* __restrict__ A,
                                        const float* __restrict__ W,
                                        float (&d)[4][8][4], float* sm) {
    const int tid  = threadIdx.x;
    const int lane = tid & 31;
    const int w    = tid >> 5;
    const int mB   = blockIdx.y << 7;
    const int nB   = blockIdx.x << 7;
    const int wm   = (w >> 1) << 6;
    const int wn   = (w & 1) << 6;
    const int g    = lane >> 2;
    const int tg   = lane & 3;

    const int r0   = tid >> 2;
    const int koff = (tid & 3) << 2;
    const float* Ag = A + (size_t)(mB + r0) * 1024 + koff;
    const float* Wg = W + (size_t)(nB + r0) * 1024 + koff;
    const unsigned sbase = (unsigned)__cvta_generic_to_shared(sm);

#define G_ISSUE(s, k0)                                                          \
    {                                                                           \
        const unsigned as_ = sbase + ((s) * G_STAGE) * 4;                       \
        const unsigned ws_ = as_ + (128 * G_STRIDE) * 4;                        \
        _Pragma("unroll")                                                       \
        for (int i = 0; i < 4; i++) {                                           \
            const unsigned so = ((r0 + 32 * i) * G_STRIDE + koff) * 4;          \
            cpa16(as_ + so, Ag + (size_t)(32 * i) * 1024 + (k0));               \
            cpa16(ws_ + so, Wg + (size_t)(32 * i) * 1024 + (k0));               \
        }                                                                       \
    }

    G_ISSUE(0, 0); cpa_commit();
    G_ISSUE(1, 16); cpa_commit();

    for (int kt = 0; kt < 64; kt++) {
        cpa_wait1();
        __syncthreads();
        if (kt + 2 < 64) {
            const int s = (kt + 2) % 3;
            G_ISSUE(s, (kt + 2) << 4);
        }
        cpa_commit();

        const float* As = sm + (kt % 3) * G_STAGE;
        const float* Ws = As + 128 * G_STRIDE;
#pragma unroll
        for (int ks = 0; ks < 2; ks++) {
            const int kb = ks << 3;
            unsigned bf[8][2];
#pragma unroll
            for (int nt = 0; nt < 8; nt++) {
                const int n = wn + (nt << 3) + g;
                bf[nt][0] = rnd(Ws[n * G_STRIDE + kb + tg]);
                bf[nt][1] = rnd(Ws[n * G_STRIDE + kb + 4 + tg]);
            }
#pragma unroll
            for (int mt = 0; mt < 4; mt++) {
                const int m = wm + (mt << 4) + g;
                unsigned a0 = rnd(As[m * G_STRIDE + kb + tg]);
                unsigned a1 = rnd(As[(m + 8) * G_STRIDE + kb + tg]);
                unsigned a2 = rnd(As[m * G_STRIDE + kb + 4 + tg]);
                unsigned a3 = rnd(As[(m + 8) * G_STRIDE + kb + 4 + tg]);
#pragma unroll
                for (int nt = 0; nt < 8; nt++)
                    mma8(d[mt][nt], a0, a1, a2, a3, bf[nt][0], bf[nt][1]);
            }
        }
    }
#undef G_ISSUE
}

// QKV projections, fused over blockIdx.z; epilogue pre-rounds for attention.
__global__ __launch_bounds__(128, 3) void gemm_qkv(const float* __restrict__ x,
                                                   const float* __restrict__ wq, const float* __restrict__ bq,
                                                   const float* __restrict__ wk, const float* __restrict__ bk,
                                                   const float* __restrict__ wv, const float* __restrict__ bv) {
    extern __shared__ float sm[];
    const int z = blockIdx.z;
    const float* W    = (z == 0) ? wq : (z == 1) ? wk : wv;
    const float* bias = (z == 0) ? bq : (z == 1) ? bk : bv;

    float d[4][8][4] = {};
    mm_body(x, W, d, sm);

    const int tid = threadIdx.x, lane = tid & 31, w = tid >> 5;
    const int mB = blockIdx.y << 7, nB = blockIdx.x << 7;
    const int wm = (w >> 1) << 6, wn = (w & 1) << 6;
    const int g = lane >> 2, tg = lane & 3;
    const float QSC = 0.125f * 1.4426950408889634f;  // 1/sqrt(64) * log2(e)
    const int p0c = ((tg & 1) << 2) | (tg >> 1);     // perm position of col 2tg

#pragma unroll
    for (int nt = 0; nt < 8; nt++) {
        const int e = nB + wn + (nt << 3) + (tg << 1);     // orig col: h*64 + hd
        const int h = e >> 6, hd = e & 63;
        const float b0 = bias[e], b1 = bias[e + 1];
        const int hdp = (hd & ~7) | p0c;
#pragma unroll
        for (int mt = 0; mt < 4; mt++)
#pragma unroll
            for (int rr = 0; rr < 2; rr++) {
                const int gm = mB + wm + (mt << 4) + g + (rr << 3);
                const int b = gm >> 11, s = gm & 2047;
                const size_t base = ((((size_t)b * NUM_H + h) * NUM_S + s) << 6);
                const float vx = d[mt][nt][rr * 2 + 0] + b0;
                const float vy = d[mt][nt][rr * 2 + 1] + b1;
                if (z == 0) {        // Q: fold scale*log2e, pre-round, d-perm
                    g_Q[base + hdp]     = rndf(QSC * vx);
                    g_Q[base + hdp + 2] = rndf(QSC * vy);
                } else if (z == 1) { // K: pre-round, d-perm
                    g_K[base + hdp]     = rndf(vx);
                    g_K[base + hdp + 2] = rndf(vy);
                } else {             // V: fp32 natural + rounded s-pair-interleaved
                    *(float2*)(g_V + base + hd) = make_float2(vx, vy);
                    const size_t pb = ((((size_t)b * NUM_H + h) * NUM_S + s) >> 1 << 7)
                                      + (s & 1);
                    g_Vp[pb + (hd << 1)]     = rndf(vx);
                    g_Vp[pb + (hd << 1) + 2] = rndf(vy);
                }
            }
    }
}

// output projection: out = g_Oc * Wo^T + bo
__global__ __launch_bounds__(128, 3) void gemm_out(const float* __restrict__ W,
                                                   const float* __restrict__ bias,
                                                   float* __restrict__ C) {
    extern __shared__ float sm[];
    float d[4][8][4] = {};
    mm_body(g_Oc, W, d, sm);

    const int tid = threadIdx.x, lane = tid & 31, w = tid >> 5;
    const int mB = blockIdx.y << 7, nB = blockIdx.x << 7;
    const int wm = (w >> 1) << 6, wn = (w & 1) << 6;
    const int g = lane >> 2, tg = lane & 3;

#pragma unroll
    for (int nt = 0; nt < 8; nt++) {
        const int e = nB + wn + (nt << 3) + (tg << 1);
        const float b0 = bias[e], b1 = bias[e + 1];
#pragma unroll
        for (int mt = 0; mt < 4; mt++)
#pragma unroll
            for (int rr = 0; rr < 2; rr++) {
                const int gm = mB + wm + (mt << 4) + g + (rr << 3);
                float2 o = make_float2(d[mt][nt][rr * 2 + 0] + b0,
                                       d[mt][nt][rr * 2 + 1] + b1);
                *(float2*)(C + (size_t)gm * NUM_D + e) = o;
            }
    }
}

// ========== tf32-mma flash attention + fused Gram-Schmidt exclusion ========
// 256 threads = 8 warps, BQ=128, BKV=64, double-buffered cp.async.
// Q/K d-permuted (LDS.64 frags); P in registers (C-frag reuse);
// V s-pair-interleaved (LDS.64 B-frags; stride 136 -> conflict-free phases).
#define ATS_P 72
#define ATS_K 72
#define ATS_V 136                       // floats per V pair-row (32 rows/tile)
#define A_K_FLOATS (64 * ATS_K)
#define A_V_FLOATS (32 * ATS_V)
#define A_STAGE_FLOATS (A_K_FLOATS + A_V_FLOATS)          // 8960
#define A_SMEM ((128 * ATS_P + 2 * A_STAGE_FLOATS) * 4)   // 108544 B

__global__ __launch_bounds__(256, 2) void attn_mma() {
    extern __shared__ float sm[];
    float (*QPs)[ATS_P] = (float(*)[ATS_P])sm;   // Q staging
    float* stages = sm + 128 * ATS_P;

    const int tid = threadIdx.x, lane = tid & 31, w = tid >> 5;
    const int g = lane >> 2, tg = lane & 3;
    const int bh = blockIdx.y, q0 = blockIdx.x << 7;
    const float* Qg  = g_Q  + (size_t)bh * NUM_S * HDIM;
    const float* Kg  = g_K  + (size_t)bh * NUM_S * HDIM;
    const float* Vg  = g_V  + (size_t)bh * NUM_S * HDIM;
    const float* Vpg = g_Vp + (size_t)bh * NUM_S * HDIM;
    const unsigned sstage = (unsigned)__cvta_generic_to_shared(stages);

    // K copy mapping: 64 rows x 64 floats; V copy: 32 pair-rows x 128 floats
    const int a_row = tid >> 4;            // K: +16 per i
    const int a_col = (tid & 15) << 2;
    const int v_row = tid >> 3;            // V: 0..31
    const int v_c0  = (tid & 7) << 2;      // + 32 words per j
#define A_ISSUE(t)                                                              \
    {                                                                           \
        const unsigned kb_ = sstage + (((t) & 1) * A_STAGE_FLOATS) * 4;         \
        const unsigned vb_ = kb_ + A_K_FLOATS * 4;                              \
        const float* kg_ = Kg + ((size_t)(t) << 12);                            \
        const float* vg_ = Vpg + ((size_t)(t) << 12);                           \
        _Pragma("unroll")                                                       \
        for (int i = 0; i < 4; i++) {                                           \
            const int r_ = a_row + (i << 4);                                    \
            cpa16(kb_ + (r_ * ATS_K + a_col) * 4, kg_ + (r_ << 6) + a_col);     \
            const int vc_ = v_c0 + (i << 5);                                    \
            cpa16(vb_ + (v_row * ATS_V + vc_) * 4, vg_ + (v_row << 7) + vc_);   \
        }                                                                       \
        cpa_commit();                                                           \
    }

    A_ISSUE(0);

    // load Q tile (already scaled + rounded + d-permuted)
    {
        const int row = tid >> 1, cb = (tid & 1) << 5;
#pragma unroll
        for (int f = 0; f < 8; f++)
            *(float4*)&QPs[row][cb + (f << 2)] =
                *(const float4*)(Qg + (size_t)(q0 + row) * 64 + cb + (f << 2));
    }
    __syncthreads();

    // extract Q fragments: perm makes (tg, tg+4) adjacent -> LDS.64
    const int qr = (w << 4) + g;
    const int kpo = tg << 1;
    unsigned qa[8][4];
#pragma unroll
    for (int ks = 0; ks < 8; ks++) {
        float2 q02 = *(const float2*)&QPs[qr][(ks << 3) + kpo];
        float2 q13 = *(const float2*)&QPs[qr + 8][(ks << 3) + kpo];
        qa[ks][0] = __float_as_uint(q02.x); qa[ks][2] = __float_as_uint(q02.y);
        qa[ks][1] = __float_as_uint(q13.x); qa[ks][3] = __float_as_uint(q13.y);
    }

    float accO[8][4];
#pragma unroll
    for (int nt = 0; nt < 8; nt++)
#pragma unroll
        for (int i = 0; i < 4; i++) accO[nt][i] = 0.f;
    float su0 = 0.f, su1 = 0.f;

    for (int t = 0; t < NUM_S / 64; t++) {
        cpa_wait0();
        __syncthreads();
        if (t + 1 < NUM_S / 64) A_ISSUE(t + 1);

        const float* Ks = stages + (t & 1) * A_STAGE_FLOATS;
        const float* Vs = Ks + A_K_FLOATS;

        // S = Q K^T  (K frag pairs via LDS.64, d-perm)
        float s_[8][4];
#pragma unroll
        for (int nt = 0; nt < 8; nt++)
#pragma unroll
            for (int i = 0; i < 4; i++) s_[nt][i] = 0.f;
#pragma unroll
        for (int ks = 0; ks < 8; ks++) {
            const int kb2 = (ks << 3) + kpo;
#pragma unroll
            for (int nt = 0; nt < 8; nt++) {
                const int n = (nt << 3) + g;
                float2 bb = *(const float2*)&Ks[n * ATS_K + kb2];
                mma8(s_[nt], qa[ks][0], qa[ks][1], qa[ks][2], qa[ks][3],
                     __float_as_uint(bb.x), __float_as_uint(bb.y));
            }
        }

        // O += numerator * V; P in registers (C-frag reuse, key-slot perm);
        // V pair rows (8ks+2tg, +1) are one float2 at Vs[(4ks+tg)*ATS_V + 2n].
#pragma unroll
        for (int ks = 0; ks < 8; ks++) {
            const float p0 = ex2(s_[ks][0]);   // (qr,   key 8ks+2tg)
            const float p1 = ex2(s_[ks][1]);   // (qr,   key 8ks+2tg+1)
            const float p2 = ex2(s_[ks][2]);   // (qr+8, key 8ks+2tg)
            const float p3 = ex2(s_[ks][3]);   // (qr+8, key 8ks+2tg+1)
            su0 += p0 + p1;
            su1 += p2 + p3;
            const unsigned a0 = rnd(p0), a1 = rnd(p2), a2 = rnd(p1), a3 = rnd(p3);
            const float* vrow = Vs + ((ks << 2) + tg) * ATS_V;
#pragma unroll
            for (int nt = 0; nt < 8; nt++) {
                const int n = (nt << 3) + g;
                float2 vv = *(const float2*)&vrow[n << 1];
                mma8(accO[nt], a0, a1, a2, a3,
                     __float_as_uint(vv.x), __float_as_uint(vv.y));
            }
        }
    }
#undef A_ISSUE

    // epilogue: row sums, normalize, Gram-Schmidt exclusion, scatter [b,s,d]
    su0 += __shfl_xor_sync(0xffffffffu, su0, 1);
    su0 += __shfl_xor_sync(0xffffffffu, su0, 2);
    su1 += __shfl_xor_sync(0xffffffffu, su1, 1);
    su1 += __shfl_xor_sync(0xffffffffu, su1, 2);
    const float i0 = 1.f / su0, i1 = 1.f / su1;

    const int b = bh >> 4, h = bh & 15;
    float v0[8][2], v1[8][2];
    float ov0 = 0.f, vv0 = 0.f, ov1 = 0.f, vv1 = 0.f;
#pragma unroll
    for (int nt = 0; nt < 8; nt++) {
        const int col = (nt << 3) + (tg << 1);
        float2 va = *(const float2*)(Vg + (size_t)(q0 + qr) * 64 + col);
        float2 vb = *(const float2*)(Vg + (size_t)(q0 + qr + 8) * 64 + col);
        accO[nt][0] *= i0; accO[nt][1] *= i0;
        accO[nt][2] *= i1; accO[nt][3] *= i1;
        v0[nt][0] = va.x; v0[nt][1] = va.y;
        v1[nt][0] = vb.x; v1[nt][1] = vb.y;
        ov0 += accO[nt][0] * va.x + accO[nt][1] * va.y;
        vv0 += va.x * va.x + va.y * va.y;
        ov1 += accO[nt][2] * vb.x + accO[nt][3] * vb.y;
        vv1 += vb.x * vb.x + vb.y * vb.y;
    }
    ov0 += __shfl_xor_sync(0xffffffffu, ov0, 1);
    ov0 += __shfl_xor_sync(0xffffffffu, ov0, 2);
    vv0 += __shfl_xor_sync(0xffffffffu, vv0, 1);
    vv0 += __shfl_xor_sync(0xffffffffu, vv0, 2);
    ov1 += __shfl_xor_sync(0xffffffffu, ov1, 1);
    ov1 += __shfl_xor_sync(0xffffffffu, ov1, 2);
    vv1 += __shfl_xor_sync(0xffffffffu, vv1, 1);
    vv1 += __shfl_xor_sync(0xffffffffu, vv1, 2);
    const float al0 = ov0 / (vv0 + 1e-8f);
    const float al1 = ov1 / (vv1 + 1e-8f);
#pragma unroll
    for (int nt = 0; nt < 8; nt++) {
        const int col = (nt << 3) + (tg << 1);
        float* dst0 = g_Oc + (size_t)(b * NUM_S + q0 + qr) * NUM_D + h * 64 + col;
        *(float2*)dst0 = make_float2(accO[nt][0] - al0 * v0[nt][0],
                                     accO[nt][1] - al0 * v0[nt][1]);
        float* dst1 = g_Oc + (size_t)(b * NUM_S + q0 + qr + 8) * NUM_D + h * 64 + col;
        *(float2*)dst1 = make_float2(accO[nt][2] - al1 * v1[nt][0],
                                     accO[nt][3] - al1 * v1[nt][1]);
    }
}

// ---------------------------------------------------------------------------
extern "C" void kernel_launch(void* const* d_in, const int* in_sizes, int n_in,
                              void* d_out, int out_size) {
    const float* x  = (const float*)d_in[0];
    const float* wq = (const float*)d_in[1];
    const float* bq = (const float*)d_in[2];
    const float* wk = (const float*)d_in[3];
    const float* bk = (const float*)d_in[4];
    const float* wv = (const float*)d_in[5];
    const float* bv = (const float*)d_in[6];
    const float* wo = (const float*)d_in[7];
    const float* bo = (const float*)d_in[8];
    float* out = (float*)d_out;

    cudaFuncSetAttribute(attn_mma, cudaFuncAttributeMaxDynamicSharedMemorySize, A_SMEM);
    cudaFuncSetAttribute(gemm_qkv, cudaFuncAttributeMaxDynamicSharedMemorySize, G_SMEM);
    cudaFuncSetAttribute(gemm_out, cudaFuncAttributeMaxDynamicSharedMemorySize, G_SMEM);

    // two dummy launches keep the ncu capture slot (-s 5 -c 1) on attn_mma
    dummy_k<<<1, 32>>>();
    dummy_k<<<1, 32>>>();
    gemm_qkv<<<dim3(8, 32, 3), 128, G_SMEM>>>(x, wq, bq, wk, bk, wv, bv);
    attn_mma<<<dim3(NUM_S / 128, NUM_B * NUM_H), 256, A_SMEM>>>();
    gemm_out<<<dim3(8, 32), 128, G_SMEM>>>(wo, bo, out);
}